// round 1
// baseline (speedup 1.0000x reference)
#include <cuda_runtime.h>
#include <math.h>

#define BN 8
#define CN 64
#define HN 256
#define WN 256
#define WINN 11
#define HP 246
#define TILE 16
#define TIN 26
#define NT2 256
#define GC 8
#define NGRP 8

#define C1V 0.01f
#define C2V 0.09f

__device__ float d_gw[WINN];
__device__ float g_xc[BN * 3 * HN * WN];
__device__ float g_rowstats[BN * HN * 8];
__device__ float g_mean[BN * 3];
__device__ float g_rstd[BN * 3];
__device__ float g_part[BN * NT2 * 192];

// ---------------------------------------------------------------------------
// Gaussian window (computed in fp64 to match numpy, normalized)
// ---------------------------------------------------------------------------
__global__ void init_gw_kernel() {
    double g[WINN];
    double s = 0.0;
    for (int i = 0; i < WINN; i++) {
        double d = (double)(i - WINN / 2);
        g[i] = exp(-d * d / (2.0 * 1.5 * 1.5));
        s += g[i];
    }
    for (int i = 0; i < WINN; i++) d_gw[i] = (float)(g[i] / s);
}

// ---------------------------------------------------------------------------
// Kernel A: per-pixel channel max/mean/min -> g_xc, per-row masked sums
// grid (HN, BN), block 256
// ---------------------------------------------------------------------------
__global__ void kA(const float* __restrict__ x, const int* __restrict__ mask) {
    int h = blockIdx.x, b = blockIdx.y;
    int w = threadIdx.x;
    const float* xp = x + (((size_t)b * CN) * HN + h) * WN + w;
    float mx = -1e30f, mn = 1e30f, sm = 0.f;
#pragma unroll 8
    for (int c = 0; c < CN; c++) {
        float v = xp[(size_t)c * HN * WN];
        mx = fmaxf(mx, v);
        mn = fminf(mn, v);
        sm += v;
    }
    float me = sm * (1.0f / 64.0f);
    size_t base = (((size_t)b * 3) * HN + h) * WN + w;
    g_xc[base] = mx;
    g_xc[base + (size_t)HN * WN] = me;
    g_xc[base + 2 * (size_t)HN * WN] = mn;

    float m = (float)mask[((size_t)b * HN + h) * WN + w];
    float vals[7] = {m, mx * m, me * m, mn * m, mx * mx * m, me * me * m, mn * mn * m};

    __shared__ float red[8][8];
    int lane = w & 31, wid = w >> 5;
#pragma unroll
    for (int i = 0; i < 7; i++) {
        float v = vals[i];
#pragma unroll
        for (int o = 16; o; o >>= 1) v += __shfl_xor_sync(0xffffffffu, v, o);
        if (lane == 0) red[wid][i] = v;
    }
    __syncthreads();
    if (w < 7) {
        float v = 0.f;
#pragma unroll
        for (int k = 0; k < 8; k++) v += red[k][w];
        g_rowstats[((size_t)b * HN + h) * 8 + w] = v;
    }
}

// ---------------------------------------------------------------------------
// Kernel A2: reduce row stats -> mean, rstd per (b, a) in double
// grid BN, block 256
// ---------------------------------------------------------------------------
__global__ void kA2() {
    int b = blockIdx.x, t = threadIdx.x;
    __shared__ double sred[8][7];
    double v[7];
#pragma unroll
    for (int i = 0; i < 7; i++) v[i] = (double)g_rowstats[((size_t)b * HN + t) * 8 + i];
    int lane = t & 31, wid = t >> 5;
#pragma unroll
    for (int i = 0; i < 7; i++) {
        double d = v[i];
#pragma unroll
        for (int o = 16; o; o >>= 1) d += __shfl_xor_sync(0xffffffffu, d, o);
        if (lane == 0) sred[wid][i] = d;
    }
    __syncthreads();
    if (t == 0) {
        double s[7];
#pragma unroll
        for (int i = 0; i < 7; i++) {
            double a = 0.0;
            for (int k = 0; k < 8; k++) a += sred[k][i];
            s[i] = a;
        }
        double n = s[0];
        for (int a = 0; a < 3; a++) {
            double mean = s[1 + a] / n;
            double var = (s[4 + a] - n * mean * mean) / (n - 1.0);
            g_mean[b * 3 + a] = (float)mean;
            g_rstd[b * 3 + a] = (float)(1.0 / sqrt(var));
        }
    }
}

// ---------------------------------------------------------------------------
// Kernel C: fused separable-blur SSIM over 16x16 output tiles
// grid (16, 16, BN), block 256, dyn smem
// ---------------------------------------------------------------------------
#define XF(a, r, cc) xf_s[((a) * TIN + (r)) * 48 + (cc)]
#define XSS(c, r, cc) xs[((c) * TIN + (r)) * 48 + (cc)]
#define HB(r, j, sc) hb[((r) * TILE + (j)) * 40 + (sc)]
#define HFB(r, j, q) hfb[((r) * TILE + (j)) * 6 + (q)]
#define SFS(py, px, q) SfS[((py) * TILE + (px)) * 8 + (q)]

#define SMEM_TOT ((3 * TIN * 48 + GC * TIN * 48 + TIN * TILE * 40 + TIN * TILE * 6 + TILE * TILE * 8 + 192) * 4)

__global__ __launch_bounds__(256, 1) void kC(const float* __restrict__ x,
                                             const int* __restrict__ mask) {
    extern __shared__ float smem[];
    float* xf_s = smem;                       // [3][26][48]
    float* xs = xf_s + 3 * TIN * 48;          // [8][26][48]
    float* hb = xs + GC * TIN * 48;           // [26][16][40]
    float* hfb = hb + TIN * TILE * 40;        // [26][16][6]
    float* SfS = hfb + TIN * TILE * 6;        // [16][16][8]
    float* s_acc = SfS + TILE * TILE * 8;     // [192] = [3][64]

    const int tx = blockIdx.x, ty = blockIdx.y, b = blockIdx.z;
    const int ox = tx * TILE, oy = ty * TILE;
    const int tid = threadIdx.x;

    float gw[WINN];
#pragma unroll
    for (int i = 0; i < WINN; i++) gw[i] = d_gw[i];

    if (tid < 192) s_acc[tid] = 0.f;

    // load xf tile: xf = (xc - mean) * rstd * mask
    {
        float mean[3], rstd[3];
#pragma unroll
        for (int a = 0; a < 3; a++) {
            mean[a] = g_mean[b * 3 + a];
            rstd[a] = g_rstd[b * 3 + a];
        }
        for (int idx = tid; idx < 3 * TIN * TIN; idx += 256) {
            int a = idx / (TIN * TIN);
            int rem = idx - a * (TIN * TIN);
            int rr = rem / TIN, cc = rem - rr * TIN;
            int gy = min(oy + rr, HN - 1), gx = min(ox + cc, WN - 1);
            float mc = (float)mask[((size_t)b * HN + gy) * WN + gx];
            float v = g_xc[(((size_t)b * 3 + a) * HN + gy) * WN + gx];
            XF(a, rr, cc) = (v - mean[a]) * rstd[a] * mc;
        }
    }
    __syncthreads();

    // phase0: horizontal conv of xf, xf^2
    for (int p = tid; p < TIN * TILE; p += 256) {
        int r = p / TILE, j = p - (p / TILE) * TILE;
        float hf[3] = {0, 0, 0}, hff[3] = {0, 0, 0};
#pragma unroll
        for (int k = 0; k < WINN; k++) {
            float wk = gw[k];
#pragma unroll
            for (int a = 0; a < 3; a++) {
                float v = XF(a, r, j + k);
                float t = wk * v;
                hf[a] += t;
                hff[a] = fmaf(t, v, hff[a]);
            }
        }
#pragma unroll
        for (int a = 0; a < 3; a++) {
            HFB(r, j, a) = hf[a];
            HFB(r, j, 3 + a) = hff[a];
        }
    }
    __syncthreads();

    // phase0b: vertical -> Sf, Sff per output pixel
    {
        int px = tid & 15, py = tid >> 4;
        float s[6] = {0, 0, 0, 0, 0, 0};
#pragma unroll
        for (int i = 0; i < WINN; i++) {
            float vi = gw[i];
#pragma unroll
            for (int q = 0; q < 6; q++) s[q] = fmaf(vi, HFB(py + i, px, q), s[q]);
        }
#pragma unroll
        for (int q = 0; q < 6; q++) SFS(py, px, q) = s[q];
    }
    // (sync after xs load below also protects SfS before first use)

    const float* xb = x + (size_t)b * CN * HN * WN;
    const int c_l = tid & 7;
    const int pxq = (tid >> 3) & 15;
    const int slot = tid >> 7;
    const bool vx = (ox + pxq) < HP;

    for (int g = 0; g < NGRP; g++) {
        int c0 = g * GC;
        // load x channel group tile
        for (int idx = tid; idx < GC * TIN * TIN; idx += 256) {
            int c = idx / (TIN * TIN);
            int rem = idx - c * (TIN * TIN);
            int rr = rem / TIN, cc = rem - rr * TIN;
            int gy = min(oy + rr, HN - 1), gx = min(ox + cc, WN - 1);
            XSS(c, rr, cc) = xb[(((size_t)(c0 + c)) * HN + gy) * WN + gx];
        }
        __syncthreads();

        // phase1: horizontal pass -> hb
        for (int p = tid; p < TIN * TILE; p += 256) {
            int r = p / TILE, j = p - (p / TILE) * TILE;
            float pa0[WINN], pa1[WINN], pa2[WINN];
#pragma unroll
            for (int k = 0; k < WINN; k++) {
                float wk = gw[k];
                pa0[k] = wk * XF(0, r, j + k);
                pa1[k] = wk * XF(1, r, j + k);
                pa2[k] = wk * XF(2, r, j + k);
            }
            float hv[40];
#pragma unroll
            for (int c = 0; c < GC; c++) {
                float hx = 0, hxx = 0, h0 = 0, h1 = 0, h2 = 0;
#pragma unroll
                for (int k = 0; k < WINN; k++) {
                    float xv = XSS(c, r, j + k);
                    float t = gw[k] * xv;
                    hx += t;
                    hxx = fmaf(t, xv, hxx);
                    h0 = fmaf(pa0[k], xv, h0);
                    h1 = fmaf(pa1[k], xv, h1);
                    h2 = fmaf(pa2[k], xv, h2);
                }
                hv[c] = hx;
                hv[8 + c] = hxx;
                hv[16 + c] = h0;
                hv[24 + c] = h1;
                hv[32 + c] = h2;
            }
            float4* dst = reinterpret_cast<float4*>(&HB(r, j, 0));
#pragma unroll
            for (int v = 0; v < 10; v++)
                dst[v] = make_float4(hv[4 * v], hv[4 * v + 1], hv[4 * v + 2], hv[4 * v + 3]);
        }
        __syncthreads();

        // phase2: vertical pass with register accumulators + ssim
        float acc[8][5];
#pragma unroll
        for (int li = 0; li < 8; li++)
#pragma unroll
            for (int s = 0; s < 5; s++) acc[li][s] = 0.f;

        const int rbase = slot * 8;
#pragma unroll
        for (int rr = 0; rr < 18; rr++) {
            int r = rbase + rr;
            float v0 = HB(r, pxq, 0 * 8 + c_l);
            float v1 = HB(r, pxq, 1 * 8 + c_l);
            float v2 = HB(r, pxq, 2 * 8 + c_l);
            float v3 = HB(r, pxq, 3 * 8 + c_l);
            float v4 = HB(r, pxq, 4 * 8 + c_l);
#pragma unroll
            for (int li = 0; li < 8; li++) {
                int kk = rr - li;
                if (kk >= 0 && kk < WINN) {
                    float vi = gw[kk];
                    acc[li][0] = fmaf(vi, v0, acc[li][0]);
                    acc[li][1] = fmaf(vi, v1, acc[li][1]);
                    acc[li][2] = fmaf(vi, v2, acc[li][2]);
                    acc[li][3] = fmaf(vi, v3, acc[li][3]);
                    acc[li][4] = fmaf(vi, v4, acc[li][4]);
                }
            }
        }

        float sacc[3] = {0.f, 0.f, 0.f};
#pragma unroll
        for (int li = 0; li < 8; li++) {
            int py = rbase + li;
            if (vx && (oy + py) < HP) {
                float mu2 = acc[li][0];
                float s2 = acc[li][1] - mu2 * mu2;
#pragma unroll
                for (int a = 0; a < 3; a++) {
                    float mu1 = SFS(py, pxq, a);
                    float s1 = SFS(py, pxq, 3 + a) - mu1 * mu1;
                    float s12 = acc[li][2 + a] - mu1 * mu2;
                    float num = (2.f * mu1 * mu2 + C1V) * (2.f * s12 + C2V);
                    float den = (mu1 * mu1 + mu2 * mu2 + C1V) * (s1 + s2 + C2V);
                    sacc[a] += num / den;
                }
            }
        }
        // reduce over the 4 px values held in this warp, then smem atomics
#pragma unroll
        for (int a = 0; a < 3; a++) {
            float v = sacc[a];
            v += __shfl_xor_sync(0xffffffffu, v, 8);
            v += __shfl_xor_sync(0xffffffffu, v, 16);
            if ((tid & 31) < 8) atomicAdd(&s_acc[a * 64 + c0 + c_l], v);
        }
        __syncthreads();
    }

    if (tid < 192)
        g_part[((size_t)b * NT2 + (ty * 16 + tx)) * 192 + tid] = s_acc[tid];
}

// ---------------------------------------------------------------------------
// Kernel D: reduce tiles -> ssim_info; conv over C; MLP head
// grid BN, block 192
// ---------------------------------------------------------------------------
__global__ void kD(const float* __restrict__ conv_w, const float* __restrict__ w1,
                   const float* __restrict__ b1, const float* __restrict__ w2,
                   const float* __restrict__ b2, float* __restrict__ out) {
    int b = blockIdx.x, t = threadIdx.x;
    __shared__ float ss[192];
    __shared__ float h0[64], h1[64];
    float sum = 0.f;
    for (int k = 0; k < NT2; k++) sum += g_part[((size_t)b * NT2 + k) * 192 + t];
    float si = sum * (1.0f / (246.0f * 246.0f));
    ss[t] = si;
    out[512 + b * 192 + t] = si;  // ssim_info after h
    __syncthreads();
    if (t < 64) {
        float acc = 0.f;
#pragma unroll
        for (int a = 0; a < 3; a++)
#pragma unroll
            for (int kh = 0; kh < 3; kh++) {
                int cc = t + kh - 1;
                if (cc >= 0 && cc < 64) acc = fmaf(ss[a * 64 + cc], conv_w[a * 3 + kh], acc);
            }
        h0[t] = fmaxf(acc, 0.f);
    }
    __syncthreads();
    if (t < 64) {
        float acc = b1[t];
#pragma unroll 8
        for (int k = 0; k < 64; k++) acc = fmaf(h0[k], w1[t * 64 + k], acc);
        h1[t] = fmaxf(acc, 0.f);
    }
    __syncthreads();
    if (t < 64) {
        float acc = b2[t];
#pragma unroll 8
        for (int k = 0; k < 64; k++) acc = fmaf(h1[k], w2[t * 64 + k], acc);
        out[b * 64 + t] = 1.f / (1.f + expf(-acc));
    }
}

// ---------------------------------------------------------------------------
extern "C" void kernel_launch(void* const* d_in, const int* in_sizes, int n_in,
                              void* d_out, int out_size) {
    const float* x = (const float*)d_in[0];
    const int* mask = (const int*)d_in[1];
    const float* conv_w = (const float*)d_in[2];
    const float* w1 = (const float*)d_in[3];
    const float* b1 = (const float*)d_in[4];
    const float* w2 = (const float*)d_in[5];
    const float* b2 = (const float*)d_in[6];
    float* out = (float*)d_out;

    cudaFuncSetAttribute(kC, cudaFuncAttributeMaxDynamicSharedMemorySize, SMEM_TOT);

    init_gw_kernel<<<1, 1>>>();
    kA<<<dim3(HN, BN), 256>>>(x, mask);
    kA2<<<BN, 256>>>();
    kC<<<dim3(16, 16, BN), 256, SMEM_TOT>>>(x, mask);
    kD<<<BN, 192>>>(conv_w, w1, b1, w2, b2, out);
}

// round 2
// speedup vs baseline: 1.3581x; 1.3581x over previous
#include <cuda_runtime.h>
#include <math.h>

#define BN 8
#define CN 64
#define HN 256
#define WN 256
#define WINN 11
#define HP 246
#define TILE 16
#define TIN 26
#define NT2 256
#define GC 4
#define NGRP 16
#define HBS 28

#define C1V 0.01f
#define C2V 0.09f

__device__ float d_gw[WINN];
__device__ float g_xc[BN * 3 * HN * WN];
__device__ float g_rowstats[BN * HN * 8];
__device__ float g_mean[BN * 3];
__device__ float g_rstd[BN * 3];
__device__ float g_part[BN * NT2 * 192];

// ---------------------------------------------------------------------------
// Gaussian window (computed in fp64 to match numpy, normalized)
// ---------------------------------------------------------------------------
__global__ void init_gw_kernel() {
    double g[WINN];
    double s = 0.0;
    for (int i = 0; i < WINN; i++) {
        double d = (double)(i - WINN / 2);
        g[i] = exp(-d * d / (2.0 * 1.5 * 1.5));
        s += g[i];
    }
    for (int i = 0; i < WINN; i++) d_gw[i] = (float)(g[i] / s);
}

// ---------------------------------------------------------------------------
// Kernel A: per-pixel channel max/mean/min -> g_xc, per-row masked sums
// grid (HN, BN), block 256
// ---------------------------------------------------------------------------
__global__ void kA(const float* __restrict__ x, const int* __restrict__ mask) {
    int h = blockIdx.x, b = blockIdx.y;
    int w = threadIdx.x;
    const float* xp = x + (((size_t)b * CN) * HN + h) * WN + w;
    float mx = -1e30f, mn = 1e30f, sm = 0.f;
#pragma unroll 8
    for (int c = 0; c < CN; c++) {
        float v = xp[(size_t)c * HN * WN];
        mx = fmaxf(mx, v);
        mn = fminf(mn, v);
        sm += v;
    }
    float me = sm * (1.0f / 64.0f);
    size_t base = (((size_t)b * 3) * HN + h) * WN + w;
    g_xc[base] = mx;
    g_xc[base + (size_t)HN * WN] = me;
    g_xc[base + 2 * (size_t)HN * WN] = mn;

    float m = (float)mask[((size_t)b * HN + h) * WN + w];
    float vals[7] = {m, mx * m, me * m, mn * m, mx * mx * m, me * me * m, mn * mn * m};

    __shared__ float red[8][8];
    int lane = w & 31, wid = w >> 5;
#pragma unroll
    for (int i = 0; i < 7; i++) {
        float v = vals[i];
#pragma unroll
        for (int o = 16; o; o >>= 1) v += __shfl_xor_sync(0xffffffffu, v, o);
        if (lane == 0) red[wid][i] = v;
    }
    __syncthreads();
    if (w < 7) {
        float v = 0.f;
#pragma unroll
        for (int k = 0; k < 8; k++) v += red[k][w];
        g_rowstats[((size_t)b * HN + h) * 8 + w] = v;
    }
}

// ---------------------------------------------------------------------------
// Kernel A2: reduce row stats -> mean, rstd per (b, a) in double
// grid BN, block 256
// ---------------------------------------------------------------------------
__global__ void kA2() {
    int b = blockIdx.x, t = threadIdx.x;
    __shared__ double sred[8][7];
    double v[7];
#pragma unroll
    for (int i = 0; i < 7; i++) v[i] = (double)g_rowstats[((size_t)b * HN + t) * 8 + i];
    int lane = t & 31, wid = t >> 5;
#pragma unroll
    for (int i = 0; i < 7; i++) {
        double d = v[i];
#pragma unroll
        for (int o = 16; o; o >>= 1) d += __shfl_xor_sync(0xffffffffu, d, o);
        if (lane == 0) sred[wid][i] = d;
    }
    __syncthreads();
    if (t == 0) {
        double s[7];
#pragma unroll
        for (int i = 0; i < 7; i++) {
            double a = 0.0;
            for (int k = 0; k < 8; k++) a += sred[k][i];
            s[i] = a;
        }
        double n = s[0];
        for (int a = 0; a < 3; a++) {
            double mean = s[1 + a] / n;
            double var = (s[4 + a] - n * mean * mean) / (n - 1.0);
            g_mean[b * 3 + a] = (float)mean;
            g_rstd[b * 3 + a] = (float)(1.0 / sqrt(var));
        }
    }
}

// ---------------------------------------------------------------------------
// Kernel C: fused separable-blur SSIM over 16x16 output tiles
// grid (16, 16, BN), block 256, dyn smem, 2 CTAs/SM
// ---------------------------------------------------------------------------
#define XF(a, r, cc) xf_s[((a) * TIN + (r)) * 48 + (cc)]
#define XSS(c, r, cc) xs[((c) * TIN + (r)) * 48 + (cc)]
#define HB(r, j, sc) hb[((r) * TILE + (j)) * HBS + (sc)]
#define HFB(r, j, q) hfb[((r) * TILE + (j)) * 6 + (q)]
#define SFS(py, px, q) SfS[((py) * TILE + (px)) * 8 + (q)]

#define SMEM_TOT ((3 * TIN * 48 + GC * TIN * 48 + TIN * TILE * HBS + TIN * TILE * 6 + TILE * TILE * 8 + 192) * 4)

__global__ __launch_bounds__(256, 2) void kC(const float* __restrict__ x,
                                             const int* __restrict__ mask) {
    extern __shared__ float smem[];
    float* xf_s = smem;                       // [3][26][48]
    float* xs = xf_s + 3 * TIN * 48;          // [4][26][48]
    float* hb = xs + GC * TIN * 48;           // [26][16][28]
    float* hfb = hb + TIN * TILE * HBS;       // [26][16][6]
    float* SfS = hfb + TIN * TILE * 6;        // [16][16][8]
    float* s_acc = SfS + TILE * TILE * 8;     // [192] = [3][64]

    const int tx = blockIdx.x, ty = blockIdx.y, b = blockIdx.z;
    const int ox = tx * TILE, oy = ty * TILE;
    const int tid = threadIdx.x;

    float gw[WINN];
#pragma unroll
    for (int i = 0; i < WINN; i++) gw[i] = d_gw[i];

    if (tid < 192) s_acc[tid] = 0.f;

    // load xf tile: xf = (xc - mean) * rstd * mask
    {
        float mean[3], rstd[3];
#pragma unroll
        for (int a = 0; a < 3; a++) {
            mean[a] = g_mean[b * 3 + a];
            rstd[a] = g_rstd[b * 3 + a];
        }
        for (int idx = tid; idx < 3 * TIN * TIN; idx += 256) {
            int a = idx / (TIN * TIN);
            int rem = idx - a * (TIN * TIN);
            int rr = rem / TIN, cc = rem - rr * TIN;
            int gy = min(oy + rr, HN - 1), gx = min(ox + cc, WN - 1);
            float mc = (float)mask[((size_t)b * HN + gy) * WN + gx];
            float v = g_xc[(((size_t)b * 3 + a) * HN + gy) * WN + gx];
            XF(a, rr, cc) = (v - mean[a]) * rstd[a] * mc;
        }
    }
    __syncthreads();

    // phase0: horizontal conv of xf, xf^2
    for (int p = tid; p < TIN * TILE; p += 256) {
        int r = p / TILE, j = p - (p / TILE) * TILE;
        float hf[3] = {0, 0, 0}, hff[3] = {0, 0, 0};
#pragma unroll
        for (int k = 0; k < WINN; k++) {
            float wk = gw[k];
#pragma unroll
            for (int a = 0; a < 3; a++) {
                float v = XF(a, r, j + k);
                float t = wk * v;
                hf[a] += t;
                hff[a] = fmaf(t, v, hff[a]);
            }
        }
#pragma unroll
        for (int a = 0; a < 3; a++) {
            HFB(r, j, a) = hf[a];
            HFB(r, j, 3 + a) = hff[a];
        }
    }
    __syncthreads();

    // phase0b: vertical -> Sf, Sff per output pixel
    {
        int px = tid & 15, py = tid >> 4;
        float s[6] = {0, 0, 0, 0, 0, 0};
#pragma unroll
        for (int i = 0; i < WINN; i++) {
            float vi = gw[i];
#pragma unroll
            for (int q = 0; q < 6; q++) s[q] = fmaf(vi, HFB(py + i, px, q), s[q]);
        }
#pragma unroll
        for (int q = 0; q < 6; q++) SFS(py, px, q) = s[q];
    }
    // (sync after xs load below also protects SfS before first use)

    const float* xb = x + (size_t)b * CN * HN * WN;
    const int c_l = tid & 3;
    const int pxq = (tid >> 2) & 15;
    const int slot = tid >> 6;          // 0..3, 4 output rows each
    const bool vx = (ox + pxq) < HP;

    for (int g = 0; g < NGRP; g++) {
        int c0 = g * GC;
        // load x channel group tile
        for (int idx = tid; idx < GC * TIN * TIN; idx += 256) {
            int c = idx / (TIN * TIN);
            int rem = idx - c * (TIN * TIN);
            int rr = rem / TIN, cc = rem - rr * TIN;
            int gy = min(oy + rr, HN - 1), gx = min(ox + cc, WN - 1);
            XSS(c, rr, cc) = xb[(((size_t)(c0 + c)) * HN + gy) * WN + gx];
        }
        __syncthreads();

        // phase1: horizontal pass -> hb
        for (int p = tid; p < TIN * TILE; p += 256) {
            int r = p / TILE, j = p - (p / TILE) * TILE;
            float pa0[WINN], pa1[WINN], pa2[WINN];
#pragma unroll
            for (int k = 0; k < WINN; k++) {
                float wk = gw[k];
                pa0[k] = wk * XF(0, r, j + k);
                pa1[k] = wk * XF(1, r, j + k);
                pa2[k] = wk * XF(2, r, j + k);
            }
            float hv[20];
#pragma unroll
            for (int c = 0; c < GC; c++) {
                float hx = 0, hxx = 0, h0 = 0, h1 = 0, h2 = 0;
#pragma unroll
                for (int k = 0; k < WINN; k++) {
                    float xv = XSS(c, r, j + k);
                    float t = gw[k] * xv;
                    hx += t;
                    hxx = fmaf(t, xv, hxx);
                    h0 = fmaf(pa0[k], xv, h0);
                    h1 = fmaf(pa1[k], xv, h1);
                    h2 = fmaf(pa2[k], xv, h2);
                }
                hv[c] = hx;
                hv[4 + c] = hxx;
                hv[8 + c] = h0;
                hv[12 + c] = h1;
                hv[16 + c] = h2;
            }
            float4* dst = reinterpret_cast<float4*>(&HB(r, j, 0));
#pragma unroll
            for (int v = 0; v < 5; v++)
                dst[v] = make_float4(hv[4 * v], hv[4 * v + 1], hv[4 * v + 2], hv[4 * v + 3]);
        }
        __syncthreads();

        // phase2: vertical pass with register accumulators + ssim
        float acc[4][5];
#pragma unroll
        for (int li = 0; li < 4; li++)
#pragma unroll
            for (int s = 0; s < 5; s++) acc[li][s] = 0.f;

        const int rbase = slot * 4;
#pragma unroll
        for (int rr = 0; rr < 14; rr++) {
            int r = rbase + rr;
            float v0 = HB(r, pxq, 0 * 4 + c_l);
            float v1 = HB(r, pxq, 1 * 4 + c_l);
            float v2 = HB(r, pxq, 2 * 4 + c_l);
            float v3 = HB(r, pxq, 3 * 4 + c_l);
            float v4 = HB(r, pxq, 4 * 4 + c_l);
#pragma unroll
            for (int li = 0; li < 4; li++) {
                int kk = rr - li;
                if (kk >= 0 && kk < WINN) {
                    float vi = gw[kk];
                    acc[li][0] = fmaf(vi, v0, acc[li][0]);
                    acc[li][1] = fmaf(vi, v1, acc[li][1]);
                    acc[li][2] = fmaf(vi, v2, acc[li][2]);
                    acc[li][3] = fmaf(vi, v3, acc[li][3]);
                    acc[li][4] = fmaf(vi, v4, acc[li][4]);
                }
            }
        }

        float sacc[3] = {0.f, 0.f, 0.f};
#pragma unroll
        for (int li = 0; li < 4; li++) {
            int py = rbase + li;
            if (vx && (oy + py) < HP) {
                float mu2 = acc[li][0];
                float s2 = acc[li][1] - mu2 * mu2;
#pragma unroll
                for (int a = 0; a < 3; a++) {
                    float mu1 = SFS(py, pxq, a);
                    float s1 = SFS(py, pxq, 3 + a) - mu1 * mu1;
                    float s12 = acc[li][2 + a] - mu1 * mu2;
                    float num = (2.f * mu1 * mu2 + C1V) * (2.f * s12 + C2V);
                    float den = (mu1 * mu1 + mu2 * mu2 + C1V) * (s1 + s2 + C2V);
                    sacc[a] += num / den;
                }
            }
        }
        // reduce over the 8 px values held in this warp, then smem atomics
#pragma unroll
        for (int a = 0; a < 3; a++) {
            float v = sacc[a];
            v += __shfl_xor_sync(0xffffffffu, v, 4);
            v += __shfl_xor_sync(0xffffffffu, v, 8);
            v += __shfl_xor_sync(0xffffffffu, v, 16);
            if ((tid & 31) < 4) atomicAdd(&s_acc[a * 64 + c0 + c_l], v);
        }
        __syncthreads();
    }

    if (tid < 192)
        g_part[((size_t)b * NT2 + (ty * 16 + tx)) * 192 + tid] = s_acc[tid];
}

// ---------------------------------------------------------------------------
// Kernel D: reduce tiles -> ssim_info; conv over C; MLP head
// grid BN, block 192
// ---------------------------------------------------------------------------
__global__ void kD(const float* __restrict__ conv_w, const float* __restrict__ w1,
                   const float* __restrict__ b1, const float* __restrict__ w2,
                   const float* __restrict__ b2, float* __restrict__ out) {
    int b = blockIdx.x, t = threadIdx.x;
    __shared__ float ss[192];
    __shared__ float h0[64], h1[64];
    float sum = 0.f;
    for (int k = 0; k < NT2; k++) sum += g_part[((size_t)b * NT2 + k) * 192 + t];
    float si = sum * (1.0f / (246.0f * 246.0f));
    ss[t] = si;
    out[512 + b * 192 + t] = si;  // ssim_info after h
    __syncthreads();
    if (t < 64) {
        float acc = 0.f;
#pragma unroll
        for (int a = 0; a < 3; a++)
#pragma unroll
            for (int kh = 0; kh < 3; kh++) {
                int cc = t + kh - 1;
                if (cc >= 0 && cc < 64) acc = fmaf(ss[a * 64 + cc], conv_w[a * 3 + kh], acc);
            }
        h0[t] = fmaxf(acc, 0.f);
    }
    __syncthreads();
    if (t < 64) {
        float acc = b1[t];
#pragma unroll 8
        for (int k = 0; k < 64; k++) acc = fmaf(h0[k], w1[t * 64 + k], acc);
        h1[t] = fmaxf(acc, 0.f);
    }
    __syncthreads();
    if (t < 64) {
        float acc = b2[t];
#pragma unroll 8
        for (int k = 0; k < 64; k++) acc = fmaf(h1[k], w2[t * 64 + k], acc);
        out[b * 64 + t] = 1.f / (1.f + expf(-acc));
    }
}

// ---------------------------------------------------------------------------
extern "C" void kernel_launch(void* const* d_in, const int* in_sizes, int n_in,
                              void* d_out, int out_size) {
    const float* x = (const float*)d_in[0];
    const int* mask = (const int*)d_in[1];
    const float* conv_w = (const float*)d_in[2];
    const float* w1 = (const float*)d_in[3];
    const float* b1 = (const float*)d_in[4];
    const float* w2 = (const float*)d_in[5];
    const float* b2 = (const float*)d_in[6];
    float* out = (float*)d_out;

    cudaFuncSetAttribute(kC, cudaFuncAttributeMaxDynamicSharedMemorySize, SMEM_TOT);

    init_gw_kernel<<<1, 1>>>();
    kA<<<dim3(HN, BN), 256>>>(x, mask);
    kA2<<<BN, 256>>>();
    kC<<<dim3(16, 16, BN), 256, SMEM_TOT>>>(x, mask);
    kD<<<BN, 192>>>(conv_w, w1, b1, w2, b2, out);
}

// round 3
// speedup vs baseline: 1.7376x; 1.2795x over previous
#include <cuda_runtime.h>
#include <math.h>

#define BN 8
#define CN 64
#define HN 256
#define WN 256
#define WINN 11
#define HP 246
#define TILE 16
#define TIN 26
#define NT2 256
#define GC 4
#define NGRP 16
#define HBS 20

#define C1V 0.01f
#define C2V 0.09f

__device__ float d_gw[WINN];
__device__ float g_xc[BN * 3 * HN * WN];
__device__ float g_rowstats[BN * HN * 8];
__device__ float g_mean[BN * 3];
__device__ float g_rstd[BN * 3];
__device__ float g_part[BN * NT2 * 192];

__device__ __forceinline__ void cpa4(float* dst, const float* src) {
    unsigned s = (unsigned)__cvta_generic_to_shared(dst);
    asm volatile("cp.async.ca.shared.global [%0],[%1],4;" ::"r"(s), "l"(src));
}
__device__ __forceinline__ void cpa8(float* dst, const float* src) {
    unsigned s = (unsigned)__cvta_generic_to_shared(dst);
    asm volatile("cp.async.ca.shared.global [%0],[%1],8;" ::"r"(s), "l"(src));
}
#define CP_COMMIT asm volatile("cp.async.commit_group;")
#define CP_WAIT asm volatile("cp.async.wait_all;")

// ---------------------------------------------------------------------------
// Gaussian window (computed in fp64 to match numpy, normalized)
// ---------------------------------------------------------------------------
__global__ void init_gw_kernel() {
    double g[WINN];
    double s = 0.0;
    for (int i = 0; i < WINN; i++) {
        double d = (double)(i - WINN / 2);
        g[i] = exp(-d * d / (2.0 * 1.5 * 1.5));
        s += g[i];
    }
    for (int i = 0; i < WINN; i++) d_gw[i] = (float)(g[i] / s);
}

// ---------------------------------------------------------------------------
// Kernel A: per-pixel channel max/mean/min -> g_xc, per-row masked sums
// ---------------------------------------------------------------------------
__global__ void kA(const float* __restrict__ x, const int* __restrict__ mask) {
    int h = blockIdx.x, b = blockIdx.y;
    int w = threadIdx.x;
    const float* xp = x + (((size_t)b * CN) * HN + h) * WN + w;
    float mx = -1e30f, mn = 1e30f, sm = 0.f;
#pragma unroll 8
    for (int c = 0; c < CN; c++) {
        float v = xp[(size_t)c * HN * WN];
        mx = fmaxf(mx, v);
        mn = fminf(mn, v);
        sm += v;
    }
    float me = sm * (1.0f / 64.0f);
    size_t base = (((size_t)b * 3) * HN + h) * WN + w;
    g_xc[base] = mx;
    g_xc[base + (size_t)HN * WN] = me;
    g_xc[base + 2 * (size_t)HN * WN] = mn;

    float m = (float)mask[((size_t)b * HN + h) * WN + w];
    float vals[7] = {m, mx * m, me * m, mn * m, mx * mx * m, me * me * m, mn * mn * m};

    __shared__ float red[8][8];
    int lane = w & 31, wid = w >> 5;
#pragma unroll
    for (int i = 0; i < 7; i++) {
        float v = vals[i];
#pragma unroll
        for (int o = 16; o; o >>= 1) v += __shfl_xor_sync(0xffffffffu, v, o);
        if (lane == 0) red[wid][i] = v;
    }
    __syncthreads();
    if (w < 7) {
        float v = 0.f;
#pragma unroll
        for (int k = 0; k < 8; k++) v += red[k][w];
        g_rowstats[((size_t)b * HN + h) * 8 + w] = v;
    }
}

// ---------------------------------------------------------------------------
// Kernel A2: reduce row stats -> mean, rstd per (b, a) in double
// ---------------------------------------------------------------------------
__global__ void kA2() {
    int b = blockIdx.x, t = threadIdx.x;
    __shared__ double sred[8][7];
    double v[7];
#pragma unroll
    for (int i = 0; i < 7; i++) v[i] = (double)g_rowstats[((size_t)b * HN + t) * 8 + i];
    int lane = t & 31, wid = t >> 5;
#pragma unroll
    for (int i = 0; i < 7; i++) {
        double d = v[i];
#pragma unroll
        for (int o = 16; o; o >>= 1) d += __shfl_xor_sync(0xffffffffu, d, o);
        if (lane == 0) sred[wid][i] = d;
    }
    __syncthreads();
    if (t == 0) {
        double s[7];
#pragma unroll
        for (int i = 0; i < 7; i++) {
            double a = 0.0;
            for (int k = 0; k < 8; k++) a += sred[k][i];
            s[i] = a;
        }
        double n = s[0];
        for (int a = 0; a < 3; a++) {
            double mean = s[1 + a] / n;
            double var = (s[4 + a] - n * mean * mean) / (n - 1.0);
            g_mean[b * 3 + a] = (float)mean;
            g_rstd[b * 3 + a] = (float)(1.0 / sqrt(var));
        }
    }
}

// ---------------------------------------------------------------------------
// Kernel C: fused separable-blur SSIM, cp.async double-buffered channel groups
// grid (16, 16, BN), block 256, 2 CTAs/SM
// ---------------------------------------------------------------------------
#define XF(a, r, cc) xf_s[((a) * TIN + (r)) * 48 + (cc)]
#define XSSB(buf, c, r, cc) (buf)[((c) * TIN + (r)) * 48 + (cc)]
#define HB(r, j, sc) hb[((r) * TILE + (j)) * HBS + (sc)]
#define HFB(r, j, q) hfb[((r) * TILE + (j)) * 6 + (q)]
#define SFS(py, px, q) SfS[((py) * TILE + (px)) * 8 + (q)]

#define XSBUF (GC * TIN * 48)
#define SMEM_TOT ((3 * TIN * 48 + 2 * XSBUF + TIN * TILE * HBS + TIN * TILE * 6 + TILE * TILE * 8 + 192) * 4)

__device__ __forceinline__ void prefetch_group(const float* __restrict__ xb, float* __restrict__ buf,
                                               int c0, int ox, int oy, int tid, bool interior) {
    if (interior) {
        for (int idx = tid; idx < GC * TIN * 13; idx += 256) {
            int c = idx / (TIN * 13);
            int rem = idx - c * (TIN * 13);
            int rr = rem / 13, q = rem - rr * 13;
            const float* src = xb + (((size_t)(c0 + c)) * HN + (oy + rr)) * WN + ox + 2 * q;
            cpa8(&XSSB(buf, c, rr, 2 * q), src);
        }
    } else {
        for (int idx = tid; idx < GC * TIN * TIN; idx += 256) {
            int c = idx / (TIN * TIN);
            int rem = idx - c * (TIN * TIN);
            int rr = rem / TIN, cc = rem - rr * TIN;
            int gy = min(oy + rr, HN - 1), gx = min(ox + cc, WN - 1);
            cpa4(&XSSB(buf, c, rr, cc), xb + (((size_t)(c0 + c)) * HN + gy) * WN + gx);
        }
    }
    CP_COMMIT;
}

__global__ __launch_bounds__(256, 2) void kC(const float* __restrict__ x,
                                             const int* __restrict__ mask) {
    extern __shared__ float smem[];
    float* xf_s = smem;                       // [3][26][48]
    float* xs0 = xf_s + 3 * TIN * 48;         // 2 x [4][26][48]
    float* hb = xs0 + 2 * XSBUF;              // [26][16][20]
    float* hfb = hb + TIN * TILE * HBS;       // [26][16][6]
    float* SfS = hfb + TIN * TILE * 6;        // [16][16][8]
    float* s_acc = SfS + TILE * TILE * 8;     // [192]

    const int tx = blockIdx.x, ty = blockIdx.y, b = blockIdx.z;
    const int ox = tx * TILE, oy = ty * TILE;
    const int tid = threadIdx.x;
    const bool interior = (ox + TIN <= WN) && (oy + TIN <= HN);
    const float* xb = x + (size_t)b * CN * HN * WN;

    float gw[WINN];
#pragma unroll
    for (int i = 0; i < WINN; i++) gw[i] = d_gw[i];

    if (tid < 192) s_acc[tid] = 0.f;

    // kick off prefetch of channel group 0 ASAP
    prefetch_group(xb, xs0, 0, ox, oy, tid, interior);

    // load xf tile: xf = (xc - mean) * rstd * mask
    {
        float mean[3], rstd[3];
#pragma unroll
        for (int a = 0; a < 3; a++) {
            mean[a] = g_mean[b * 3 + a];
            rstd[a] = g_rstd[b * 3 + a];
        }
        for (int idx = tid; idx < 3 * TIN * TIN; idx += 256) {
            int a = idx / (TIN * TIN);
            int rem = idx - a * (TIN * TIN);
            int rr = rem / TIN, cc = rem - rr * TIN;
            int gy = min(oy + rr, HN - 1), gx = min(ox + cc, WN - 1);
            float mc = (float)mask[((size_t)b * HN + gy) * WN + gx];
            float v = g_xc[(((size_t)b * 3 + a) * HN + gy) * WN + gx];
            XF(a, rr, cc) = (v - mean[a]) * rstd[a] * mc;
        }
    }
    __syncthreads();

    // phase0: horizontal conv of xf, xf^2
    for (int p = tid; p < TIN * TILE; p += 256) {
        int r = p / TILE, j = p - (p / TILE) * TILE;
        float hf[3] = {0, 0, 0}, hff[3] = {0, 0, 0};
#pragma unroll
        for (int k = 0; k < WINN; k++) {
            float wk = gw[k];
#pragma unroll
            for (int a = 0; a < 3; a++) {
                float v = XF(a, r, j + k);
                float t = wk * v;
                hf[a] += t;
                hff[a] = fmaf(t, v, hff[a]);
            }
        }
#pragma unroll
        for (int a = 0; a < 3; a++) {
            HFB(r, j, a) = hf[a];
            HFB(r, j, 3 + a) = hff[a];
        }
    }
    __syncthreads();

    // phase0b: vertical -> Sf, Sff per output pixel
    {
        int px = tid & 15, py = tid >> 4;
        float s[6] = {0, 0, 0, 0, 0, 0};
#pragma unroll
        for (int i = 0; i < WINN; i++) {
            float vi = gw[i];
#pragma unroll
            for (int q = 0; q < 6; q++) s[q] = fmaf(vi, HFB(py + i, px, q), s[q]);
        }
#pragma unroll
        for (int q = 0; q < 6; q++) SFS(py, px, q) = s[q];
    }
    CP_WAIT;
    __syncthreads();  // group-0 tile + SfS visible to all

    const int c_l = tid & 3;
    const int pxq = (tid >> 2) & 15;
    const int slot = tid >> 6;
    const bool vx = (ox + pxq) < HP;

    for (int g = 0; g < NGRP; g++) {
        float* xs = xs0 + (g & 1) * XSBUF;
        if (g + 1 < NGRP)
            prefetch_group(xb, xs0 + ((g + 1) & 1) * XSBUF, (g + 1) * GC, ox, oy, tid, interior);
        int c0 = g * GC;

        // phase1: horizontal pass -> hb
        for (int p = tid; p < TIN * TILE; p += 256) {
            int r = p / TILE, j = p - (p / TILE) * TILE;
            float pa0[WINN], pa1[WINN], pa2[WINN];
#pragma unroll
            for (int k = 0; k < WINN; k++) {
                float wk = gw[k];
                pa0[k] = wk * XF(0, r, j + k);
                pa1[k] = wk * XF(1, r, j + k);
                pa2[k] = wk * XF(2, r, j + k);
            }
            float hv[20];
#pragma unroll
            for (int c = 0; c < GC; c++) {
                float hx = 0, hxx = 0, h0 = 0, h1 = 0, h2 = 0;
#pragma unroll
                for (int k = 0; k < WINN; k++) {
                    float xv = XSSB(xs, c, r, j + k);
                    float t = gw[k] * xv;
                    hx += t;
                    hxx = fmaf(t, xv, hxx);
                    h0 = fmaf(pa0[k], xv, h0);
                    h1 = fmaf(pa1[k], xv, h1);
                    h2 = fmaf(pa2[k], xv, h2);
                }
                hv[c] = hx;
                hv[4 + c] = hxx;
                hv[8 + c] = h0;
                hv[12 + c] = h1;
                hv[16 + c] = h2;
            }
            float4* dst = reinterpret_cast<float4*>(&HB(r, j, 0));
#pragma unroll
            for (int v = 0; v < 5; v++)
                dst[v] = make_float4(hv[4 * v], hv[4 * v + 1], hv[4 * v + 2], hv[4 * v + 3]);
        }
        __syncthreads();

        // phase2: vertical pass with register accumulators + ssim
        float acc[4][5];
#pragma unroll
        for (int li = 0; li < 4; li++)
#pragma unroll
            for (int s = 0; s < 5; s++) acc[li][s] = 0.f;

        const int rbase = slot * 4;
#pragma unroll
        for (int rr = 0; rr < 14; rr++) {
            int r = rbase + rr;
            float v0 = HB(r, pxq, 0 * 4 + c_l);
            float v1 = HB(r, pxq, 1 * 4 + c_l);
            float v2 = HB(r, pxq, 2 * 4 + c_l);
            float v3 = HB(r, pxq, 3 * 4 + c_l);
            float v4 = HB(r, pxq, 4 * 4 + c_l);
#pragma unroll
            for (int li = 0; li < 4; li++) {
                int kk = rr - li;
                if (kk >= 0 && kk < WINN) {
                    float vi = gw[kk];
                    acc[li][0] = fmaf(vi, v0, acc[li][0]);
                    acc[li][1] = fmaf(vi, v1, acc[li][1]);
                    acc[li][2] = fmaf(vi, v2, acc[li][2]);
                    acc[li][3] = fmaf(vi, v3, acc[li][3]);
                    acc[li][4] = fmaf(vi, v4, acc[li][4]);
                }
            }
        }

        float sacc[3] = {0.f, 0.f, 0.f};
#pragma unroll
        for (int li = 0; li < 4; li++) {
            int py = rbase + li;
            if (vx && (oy + py) < HP) {
                float mu2 = acc[li][0];
                float s2 = acc[li][1] - mu2 * mu2;
#pragma unroll
                for (int a = 0; a < 3; a++) {
                    float mu1 = SFS(py, pxq, a);
                    float s1 = SFS(py, pxq, 3 + a) - mu1 * mu1;
                    float s12 = acc[li][2 + a] - mu1 * mu2;
                    float num = (2.f * mu1 * mu2 + C1V) * (2.f * s12 + C2V);
                    float den = (mu1 * mu1 + mu2 * mu2 + C1V) * (s1 + s2 + C2V);
                    sacc[a] += num / den;
                }
            }
        }
#pragma unroll
        for (int a = 0; a < 3; a++) {
            float v = sacc[a];
            v += __shfl_xor_sync(0xffffffffu, v, 4);
            v += __shfl_xor_sync(0xffffffffu, v, 8);
            v += __shfl_xor_sync(0xffffffffu, v, 16);
            if ((tid & 31) < 4) atomicAdd(&s_acc[a * 64 + c0 + c_l], v);
        }
        CP_WAIT;          // next group's tile arrived (this thread's copies)
        __syncthreads();  // visible to all; hb free for overwrite
    }

    if (tid < 192)
        g_part[((size_t)b * NT2 + (ty * 16 + tx)) * 192 + tid] = s_acc[tid];
}

// ---------------------------------------------------------------------------
// Kernel D: reduce tiles -> ssim_info; conv over C; MLP head
// ---------------------------------------------------------------------------
__global__ void kD(const float* __restrict__ conv_w, const float* __restrict__ w1,
                   const float* __restrict__ b1, const float* __restrict__ w2,
                   const float* __restrict__ b2, float* __restrict__ out) {
    int b = blockIdx.x, t = threadIdx.x;
    __shared__ float ss[192];
    __shared__ float h0[64], h1[64];
    float sum = 0.f;
    for (int k = 0; k < NT2; k++) sum += g_part[((size_t)b * NT2 + k) * 192 + t];
    float si = sum * (1.0f / (246.0f * 246.0f));
    ss[t] = si;
    out[512 + b * 192 + t] = si;  // ssim_info after h
    __syncthreads();
    if (t < 64) {
        float acc = 0.f;
#pragma unroll
        for (int a = 0; a < 3; a++)
#pragma unroll
            for (int kh = 0; kh < 3; kh++) {
                int cc = t + kh - 1;
                if (cc >= 0 && cc < 64) acc = fmaf(ss[a * 64 + cc], conv_w[a * 3 + kh], acc);
            }
        h0[t] = fmaxf(acc, 0.f);
    }
    __syncthreads();
    if (t < 64) {
        float acc = b1[t];
#pragma unroll 8
        for (int k = 0; k < 64; k++) acc = fmaf(h0[k], w1[t * 64 + k], acc);
        h1[t] = fmaxf(acc, 0.f);
    }
    __syncthreads();
    if (t < 64) {
        float acc = b2[t];
#pragma unroll 8
        for (int k = 0; k < 64; k++) acc = fmaf(h1[k], w2[t * 64 + k], acc);
        out[b * 64 + t] = 1.f / (1.f + expf(-acc));
    }
}

// ---------------------------------------------------------------------------
extern "C" void kernel_launch(void* const* d_in, const int* in_sizes, int n_in,
                              void* d_out, int out_size) {
    const float* x = (const float*)d_in[0];
    const int* mask = (const int*)d_in[1];
    const float* conv_w = (const float*)d_in[2];
    const float* w1 = (const float*)d_in[3];
    const float* b1 = (const float*)d_in[4];
    const float* w2 = (const float*)d_in[5];
    const float* b2 = (const float*)d_in[6];
    float* out = (float*)d_out;

    cudaFuncSetAttribute(kC, cudaFuncAttributeMaxDynamicSharedMemorySize, SMEM_TOT);

    init_gw_kernel<<<1, 1>>>();
    kA<<<dim3(HN, BN), 256>>>(x, mask);
    kA2<<<BN, 256>>>();
    kC<<<dim3(16, 16, BN), 256, SMEM_TOT>>>(x, mask);
    kD<<<BN, 192>>>(conv_w, w1, b1, w2, b2, out);
}